// round 1
// baseline (speedup 1.0000x reference)
#include <cuda_runtime.h>
#include <math.h>

#define NN 50000
#define RR 6
#define EE 32768
#define HH 256
#define FF 16
#define NHH 8
#define HDD 32
#define KVIN (HH + FF)      // 272

// ---------------- scratch (device globals; no allocation) ----------------
__device__ float g_kvin[EE * KVIN];
__device__ float g_xdst[EE * HH];
__device__ float g_kb[EE * HH];
__device__ float g_vb[EE * HH];
__device__ float g_qb[EE * HH];
__device__ float g_scores[EE * NHH];
__device__ float g_denom[NN * NHH];
__device__ unsigned g_key[NN * NHH];
__device__ float g_agg[NN * HH];
__device__ float g_relout[(size_t)NN * RR * HH];   // [N, R*H] == all_rel
__device__ float g_h[NN * HH];
__device__ float g_paths[NN * 3 * HH];
__device__ float g_stacked[NN * 3 * HH];
__device__ float g_t[NN * 3 * (HH / 2)];
__device__ float g_interagg[NN * HH];
__device__ float g_combin[NN * 2 * HH];
__device__ float g_comb[NN * HH];

__device__ __forceinline__ float gelu_exact(float x) {
    return 0.5f * x * (1.0f + erff(x * 0.70710678118654752f));
}

// order-preserving float<->uint for atomicMax
__device__ __forceinline__ unsigned enc_f(float f) {
    unsigned b = __float_as_uint(f);
    return (b & 0x80000000u) ? ~b : (b | 0x80000000u);
}
__device__ __forceinline__ float dec_f(unsigned u) {
    return (u & 0x80000000u) ? __uint_as_float(u ^ 0x80000000u)
                             : __uint_as_float(~u);
}

// ---------------- generic fp32 GEMM: C = act(A@B + bias) ----------------
// A: [M,K] lda, B: [K,Nc] ldb=Nc, C: [M,Nc slice] ldc. Nc%64==0, K%16==0.
// act: 0=none 1=gelu 2=tanh
__global__ void sgemm_kernel(const float* __restrict__ A, int lda,
                             const float* __restrict__ B, int ldb,
                             const float* __restrict__ bias,
                             float* __restrict__ C, int ldc,
                             int M, int Nc, int K, int act)
{
    __shared__ float As[16][128];
    __shared__ float Bs[16][64];
    const int tid = threadIdx.x;         // 256 threads
    const int tx = tid & 15;             // 0..15 (4 cols each)
    const int ty = tid >> 4;             // 0..15 (8 rows each)
    const int rowBase = blockIdx.y * 128;
    const int colBase = blockIdx.x * 64;

    float acc[8][4];
#pragma unroll
    for (int i = 0; i < 8; i++)
#pragma unroll
        for (int j = 0; j < 4; j++) acc[i][j] = 0.0f;

    for (int k0 = 0; k0 < K; k0 += 16) {
        // load A tile (128x16) as float4, store transposed
#pragma unroll
        for (int l = 0; l < 2; l++) {
            int i = tid + l * 256;
            int r = i >> 2;
            int kk = (i & 3) << 2;
            float4 a;
            if (rowBase + r < M)
                a = *(const float4*)&A[(size_t)(rowBase + r) * lda + k0 + kk];
            else
                a = make_float4(0.f, 0.f, 0.f, 0.f);
            As[kk + 0][r] = a.x; As[kk + 1][r] = a.y;
            As[kk + 2][r] = a.z; As[kk + 3][r] = a.w;
        }
        // load B tile (16x64)
        {
            int r = tid >> 4;
            int cc = (tid & 15) << 2;
            float4 b = *(const float4*)&B[(size_t)(k0 + r) * ldb + colBase + cc];
            *(float4*)&Bs[r][cc] = b;
        }
        __syncthreads();
#pragma unroll
        for (int k = 0; k < 16; k++) {
            float4 a0 = *(const float4*)&As[k][ty * 8];
            float4 a1 = *(const float4*)&As[k][ty * 8 + 4];
            float4 b  = *(const float4*)&Bs[k][tx * 4];
            float ra[8] = {a0.x, a0.y, a0.z, a0.w, a1.x, a1.y, a1.z, a1.w};
            float rb[4] = {b.x, b.y, b.z, b.w};
#pragma unroll
            for (int i = 0; i < 8; i++)
#pragma unroll
                for (int j = 0; j < 4; j++)
                    acc[i][j] = fmaf(ra[i], rb[j], acc[i][j]);
        }
        __syncthreads();
    }

#pragma unroll
    for (int i = 0; i < 8; i++) {
        int r = rowBase + ty * 8 + i;
        if (r >= M) continue;
#pragma unroll
        for (int j = 0; j < 4; j++) {
            int c = colBase + tx * 4 + j;
            float v = acc[i][j] + bias[c];
            if (act == 1) v = gelu_exact(v);
            else if (act == 2) v = tanhf(v);
            C[(size_t)r * ldc + c] = v;
        }
    }
}

// ---------------- per-relation kernels ----------------
__global__ void gather_kernel(const float* __restrict__ x,
                              const int* __restrict__ ei_r,
                              const float* __restrict__ ea_r)
{
    int e = blockIdx.x, t = threadIdx.x;   // 256 threads
    int src = ei_r[e];
    int dst = ei_r[EE + e];
    g_kvin[e * KVIN + t] = x[(size_t)src * HH + t];
    g_xdst[e * HH + t]   = x[(size_t)dst * HH + t];
    if (t < FF) g_kvin[e * KVIN + HH + t] = ea_r[e * FF + t];
}

__global__ void init_rel_kernel()
{
    int idx = blockIdx.x * 256 + threadIdx.x;   // grid = NN
    g_agg[idx] = 0.0f;
    if (idx < NN * NHH) { g_denom[idx] = 0.0f; g_key[idx] = 0u; }
}

__global__ void score_kernel(const int* __restrict__ dst_r,
                             const float* __restrict__ prior_r)
{
    int e = blockIdx.x, t = threadIdx.x;
    int h = t >> 5, lane = t & 31;
    float p = g_qb[e * HH + t] * g_kb[e * HH + t];
#pragma unroll
    for (int o = 16; o > 0; o >>= 1) p += __shfl_down_sync(0xFFFFFFFFu, p, o);
    if (lane == 0) {
        int dst = dst_r[e];
        float s = p * 0.17677669529663689f * prior_r[h];  // 1/sqrt(32)
        g_scores[e * NHH + h] = s;
        atomicMax(&g_key[dst * NHH + h], enc_f(s));
    }
}

__global__ void ex_kernel(const int* __restrict__ dst_r)
{
    int idx = blockIdx.x * 256 + threadIdx.x;   // E*NH threads
    int e = idx >> 3, h = idx & 7;
    int dst = dst_r[e];
    float m = dec_f(g_key[dst * NHH + h]);
    float ex = expf(g_scores[idx] - m);
    g_scores[idx] = ex;
    atomicAdd(&g_denom[dst * NHH + h], ex);
}

__global__ void scatter_kernel(const int* __restrict__ dst_r)
{
    int e = blockIdx.x, t = threadIdx.x;
    int h = t >> 5;
    int dst = dst_r[e];
    float w = g_scores[e * NHH + h] / (g_denom[dst * NHH + h] + 1e-16f);
    atomicAdd(&g_agg[(size_t)dst * HH + t], w * g_vb[e * HH + t]);
}

// ---------------- inter-relation fusion ----------------
__global__ void inter_kernel(const float* __restrict__ Wir2,
                             const float* __restrict__ bir2)
{
    int n = blockIdx.x, t = threadIdx.x;
    int w = t >> 5, lane = t & 31;
    __shared__ float logit[RR];
    if (w < RR) {
        float s = 0.0f;
        for (int i = lane; i < HH; i += 32)
            s += g_h[(size_t)n * HH + i] * Wir2[i * RR + w];
#pragma unroll
        for (int o = 16; o > 0; o >>= 1) s += __shfl_down_sync(0xFFFFFFFFu, s, o);
        if (lane == 0) logit[w] = s + bir2[w];
    }
    __syncthreads();
    float l[RR]; float mx = -1e30f;
#pragma unroll
    for (int r = 0; r < RR; r++) { l[r] = logit[r]; mx = fmaxf(mx, l[r]); }
    float sum = 0.0f;
#pragma unroll
    for (int r = 0; r < RR; r++) { l[r] = expf(l[r] - mx); sum += l[r]; }
    float inv = 1.0f / sum;
    int c = t;
    const float* ro = g_relout + (size_t)n * (RR * HH);
    float acc = 0.0f;
#pragma unroll
    for (int r = 0; r < RR; r++) acc += l[r] * inv * ro[r * HH + c];
    g_interagg[(size_t)n * HH + c] = acc;
    // meta-paths: 0=rel2+rel3, 1=rel4+rel0, 2=rel1+rel5
    float* pp = g_paths + (size_t)n * 3 * HH;
    pp[c]            = ro[2 * HH + c] + ro[3 * HH + c];
    pp[HH + c]       = ro[4 * HH + c] + ro[0 * HH + c];
    pp[2 * HH + c]   = ro[1 * HH + c] + ro[5 * HH + c];
}

__global__ void meta_kernel(const float* __restrict__ Wa2,
                            const float* __restrict__ gm,
                            const float* __restrict__ bm_)
{
    int n = blockIdx.x, t = threadIdx.x;
    int w = t >> 5, lane = t & 31;
    __shared__ float sl[3];
    __shared__ float red[HH];
    __shared__ float s_mu, s_var;
    if (w < 3) {
        float s = 0.0f;
        for (int i = lane; i < HH / 2; i += 32)
            s += g_t[((size_t)n * 3 + w) * (HH / 2) + i] * Wa2[i];
#pragma unroll
        for (int o = 16; o > 0; o >>= 1) s += __shfl_down_sync(0xFFFFFFFFu, s, o);
        if (lane == 0) sl[w] = s;
    }
    __syncthreads();
    float a0 = sl[0], a1 = sl[1], a2 = sl[2];
    float mx = fmaxf(a0, fmaxf(a1, a2));
    float e0 = expf(a0 - mx), e1 = expf(a1 - mx), e2 = expf(a2 - mx);
    float inv = 1.0f / (e0 + e1 + e2);
    int c = t;
    const float* st = g_stacked + (size_t)n * 3 * HH;
    float mpre = (e0 * st[c] + e1 * st[HH + c] + e2 * st[2 * HH + c]) * inv;
    // LayerNorm over 256
    red[t] = mpre; __syncthreads();
    for (int s = 128; s > 0; s >>= 1) { if (t < s) red[t] += red[t + s]; __syncthreads(); }
    if (t == 0) s_mu = red[0] * (1.0f / HH);
    __syncthreads();
    float d = mpre - s_mu;
    red[t] = d * d; __syncthreads();
    for (int s = 128; s > 0; s >>= 1) { if (t < s) red[t] += red[t + s]; __syncthreads(); }
    if (t == 0) s_var = red[0] * (1.0f / HH);
    __syncthreads();
    float meta = d * rsqrtf(s_var + 1e-5f) * gm[c] + bm_[c];
    g_combin[(size_t)n * 2 * HH + c]      = g_interagg[(size_t)n * HH + c];
    g_combin[(size_t)n * 2 * HH + HH + c] = meta;
}

__global__ void final_kernel(const float* __restrict__ x,
                             const float* __restrict__ g,
                             const float* __restrict__ b,
                             float* __restrict__ out)
{
    int n = blockIdx.x, t = threadIdx.x;
    __shared__ float red[HH];
    __shared__ float s_mu, s_var;
    float v = x[(size_t)n * HH + t] + g_comb[(size_t)n * HH + t];
    red[t] = v; __syncthreads();
    for (int s = 128; s > 0; s >>= 1) { if (t < s) red[t] += red[t + s]; __syncthreads(); }
    if (t == 0) s_mu = red[0] * (1.0f / HH);
    __syncthreads();
    float d = v - s_mu;
    red[t] = d * d; __syncthreads();
    for (int s = 128; s > 0; s >>= 1) { if (t < s) red[t] += red[t + s]; __syncthreads(); }
    if (t == 0) s_var = red[0] * (1.0f / HH);
    __syncthreads();
    out[(size_t)n * HH + t] = d * rsqrtf(s_var + 1e-5f) * g[t] + b[t];
}

// ---------------- host launcher ----------------
static inline void run_sgemm(const float* A, int lda, const float* B, int ldb,
                             const float* bias, float* C, int ldc,
                             int M, int Nc, int K, int act)
{
    dim3 grid((Nc + 63) / 64, (M + 127) / 128);
    sgemm_kernel<<<grid, 256>>>(A, lda, B, ldb, bias, C, ldc, M, Nc, K, act);
}

extern "C" void kernel_launch(void* const* d_in, const int* in_sizes, int n_in,
                              void* d_out, int out_size)
{
    const float* x    = (const float*)d_in[0];
    const int*   ei   = (const int*)d_in[1];
    const float* ea   = (const float*)d_in[2];
    const float* Wq   = (const float*)d_in[3];
    const float* bq   = (const float*)d_in[4];
    const float* Wk   = (const float*)d_in[5];
    const float* bk   = (const float*)d_in[6];
    const float* Wv   = (const float*)d_in[7];
    const float* bv   = (const float*)d_in[8];
    const float* prior= (const float*)d_in[9];
    const float* Wm   = (const float*)d_in[10];
    const float* bm   = (const float*)d_in[11];
    const float* Wir1 = (const float*)d_in[12];
    const float* bir1 = (const float*)d_in[13];
    const float* Wir2 = (const float*)d_in[14];
    const float* bir2 = (const float*)d_in[15];
    const float* Wmp  = (const float*)d_in[16];
    const float* bmp  = (const float*)d_in[17];
    const float* Wa1  = (const float*)d_in[18];
    const float* ba1  = (const float*)d_in[19];
    const float* Wa2  = (const float*)d_in[20];
    const float* gme  = (const float*)d_in[21];
    const float* bme  = (const float*)d_in[22];
    const float* Wc   = (const float*)d_in[23];
    const float* bc   = (const float*)d_in[24];
    const float* gout = (const float*)d_in[25];
    const float* bout = (const float*)d_in[26];
    float* out = (float*)d_out;

    float *p_kvin, *p_xdst, *p_kb, *p_vb, *p_qb, *p_agg, *p_relout, *p_h,
          *p_paths, *p_stacked, *p_t, *p_combin, *p_comb;
    cudaGetSymbolAddress((void**)&p_kvin, g_kvin);
    cudaGetSymbolAddress((void**)&p_xdst, g_xdst);
    cudaGetSymbolAddress((void**)&p_kb, g_kb);
    cudaGetSymbolAddress((void**)&p_vb, g_vb);
    cudaGetSymbolAddress((void**)&p_qb, g_qb);
    cudaGetSymbolAddress((void**)&p_agg, g_agg);
    cudaGetSymbolAddress((void**)&p_relout, g_relout);
    cudaGetSymbolAddress((void**)&p_h, g_h);
    cudaGetSymbolAddress((void**)&p_paths, g_paths);
    cudaGetSymbolAddress((void**)&p_stacked, g_stacked);
    cudaGetSymbolAddress((void**)&p_t, g_t);
    cudaGetSymbolAddress((void**)&p_combin, g_combin);
    cudaGetSymbolAddress((void**)&p_comb, g_comb);

    for (int r = 0; r < RR; r++) {
        const int* ei_r  = ei + (size_t)r * 2 * EE;
        const int* dst_r = ei_r + EE;
        const float* ea_r = ea + (size_t)r * EE * FF;

        gather_kernel<<<EE, 256>>>(x, ei_r, ea_r);
        run_sgemm(p_kvin, KVIN, Wk + (size_t)r * KVIN * HH, HH, bk + r * HH,
                  p_kb, HH, EE, HH, KVIN, 0);
        run_sgemm(p_kvin, KVIN, Wv + (size_t)r * KVIN * HH, HH, bv + r * HH,
                  p_vb, HH, EE, HH, KVIN, 0);
        run_sgemm(p_xdst, HH, Wq + (size_t)r * HH * HH, HH, bq + r * HH,
                  p_qb, HH, EE, HH, HH, 0);
        init_rel_kernel<<<NN, 256>>>();
        score_kernel<<<EE, 256>>>(dst_r, prior + r * NHH);
        ex_kernel<<<(EE * NHH) / 256, 256>>>(dst_r);
        scatter_kernel<<<EE, 256>>>(dst_r);
        // rel_out[r] = gelu(agg @ Wm + bm) -> column slice of [N, R*H]
        run_sgemm(p_agg, HH, Wm + (size_t)r * HH * HH, HH, bm + r * HH,
                  p_relout + r * HH, RR * HH, NN, HH, HH, 1);
    }

    // h = gelu(all_rel @ W_ir1 + b_ir1)
    run_sgemm(p_relout, RR * HH, Wir1, HH, bir1, p_h, HH, NN, HH, RR * HH, 1);
    // inter softmax + inter_agg + meta-path sums
    inter_kernel<<<NN, 256>>>(Wir2, bir2);
    // stacked[p] = paths[p] @ Wmp[p] + bmp[p]
    for (int p = 0; p < 3; p++)
        run_sgemm(p_paths + p * HH, 3 * HH, Wmp + (size_t)p * HH * HH, HH,
                  bmp + p * HH, p_stacked + p * HH, 3 * HH, NN, HH, HH, 0);
    // t = tanh(stacked @ Wa1 + ba1), rows = (n,p)
    run_sgemm(p_stacked, HH, Wa1, HH / 2, ba1, p_t, HH / 2, 3 * NN, HH / 2, HH, 2);
    // meta attention + LN + build combined input
    meta_kernel<<<NN, 256>>>(Wa2, gme, bme);
    // combined = gelu([inter_agg, meta] @ Wc + bc)
    run_sgemm(p_combin, 2 * HH, Wc, HH, bc, p_comb, HH, NN, HH, 2 * HH, 1);
    // out = LN(x + combined)
    final_kernel<<<NN, 256>>>(x, gout, bout, out);
}

// round 2
// speedup vs baseline: 1.4819x; 1.4819x over previous
#include <cuda_runtime.h>
#include <cuda_bf16.h>
#include <math.h>

#define NN 50000
#define RR 6
#define EE 32768
#define HH 256
#define FF 16
#define NHH 8
#define HDD 32
#define KVIN (HH + FF)      // 272

// ---------------- scratch (device globals; no allocation) ----------------
__device__ float g_kvin[EE * KVIN];
__device__ float g_xdst[EE * HH];
__device__ float g_kb[EE * HH];
__device__ float g_vb[EE * HH];
__device__ float g_qb[EE * HH];
__device__ float g_scores[EE * NHH];
__device__ float g_denom[NN * NHH];
__device__ unsigned g_key[NN * NHH];
__device__ float g_agg[NN * HH];
__device__ float g_relout[(size_t)NN * RR * HH];   // [N, R*H] == all_rel
__device__ float g_h[NN * HH];
__device__ float g_paths[NN * 3 * HH];
__device__ float g_stacked[NN * 3 * HH];
__device__ float g_t[NN * 3 * (HH / 2)];
__device__ float g_interagg[NN * HH];
__device__ float g_combin[NN * 2 * HH];
__device__ float g_comb[NN * HH];

__device__ __forceinline__ float gelu_exact(float x) {
    return 0.5f * x * (1.0f + erff(x * 0.70710678118654752f));
}

// order-preserving float<->uint for atomicMax
__device__ __forceinline__ unsigned enc_f(float f) {
    unsigned b = __float_as_uint(f);
    return (b & 0x80000000u) ? ~b : (b | 0x80000000u);
}
__device__ __forceinline__ float dec_f(unsigned u) {
    return (u & 0x80000000u) ? __uint_as_float(u ^ 0x80000000u)
                             : __uint_as_float(~u);
}

// ================= tensor-core GEMM (bf16 split, fp32 accurate) ==========
// C[M,Nc] = act(A[M,K] @ B[K,Nc] + bias), lda/ldb/ldc given.
// Requires Nc % 128 == 0, K % 16 == 0. act: 0=none 1=gelu 2=tanh
#define RS_A 24     // A smem row stride (bf16 elems), 16 + 8 pad
#define RS_B 136    // B smem row stride (bf16 elems), 128 + 8 pad

__device__ __forceinline__ void ldsm_x4(unsigned& r0, unsigned& r1,
                                        unsigned& r2, unsigned& r3,
                                        unsigned addr) {
    asm volatile("ldmatrix.sync.aligned.m8n8.x4.shared.b16 {%0,%1,%2,%3}, [%4];"
                 : "=r"(r0), "=r"(r1), "=r"(r2), "=r"(r3) : "r"(addr));
}
__device__ __forceinline__ void ldsm_x4t(unsigned& r0, unsigned& r1,
                                         unsigned& r2, unsigned& r3,
                                         unsigned addr) {
    asm volatile("ldmatrix.sync.aligned.m8n8.x4.trans.shared.b16 {%0,%1,%2,%3}, [%4];"
                 : "=r"(r0), "=r"(r1), "=r"(r2), "=r"(r3) : "r"(addr));
}
__device__ __forceinline__ void mma16816(float* c, const unsigned* a,
                                         unsigned b0, unsigned b1) {
    asm volatile(
        "mma.sync.aligned.m16n8k16.row.col.f32.bf16.bf16.f32 "
        "{%0,%1,%2,%3},{%4,%5,%6,%7},{%8,%9},{%0,%1,%2,%3};"
        : "+f"(c[0]), "+f"(c[1]), "+f"(c[2]), "+f"(c[3])
        : "r"(a[0]), "r"(a[1]), "r"(a[2]), "r"(a[3]), "r"(b0), "r"(b1));
}

__global__ __launch_bounds__(256)
void mma_gemm_kernel(const float* __restrict__ A, int lda,
                     const float* __restrict__ B, int ldb,
                     const float* __restrict__ bias,
                     float* __restrict__ C, int ldc,
                     int M, int Nc, int K, int act)
{
    __shared__ __align__(16) __nv_bfloat16 As_hi[128 * RS_A];
    __shared__ __align__(16) __nv_bfloat16 As_lo[128 * RS_A];
    __shared__ __align__(16) __nv_bfloat16 Bs_hi[16 * RS_B];
    __shared__ __align__(16) __nv_bfloat16 Bs_lo[16 * RS_B];

    const int tid = threadIdx.x;
    const int lane = tid & 31;
    const int w = tid >> 5;
    const int wm = w & 3;          // 4 warps along M (32 rows each)
    const int wn = w >> 2;         // 2 warps along N (64 cols each)
    const int rowBase = blockIdx.y * 128;
    const int colBase = blockIdx.x * 128;

    float acc[2][8][4];
#pragma unroll
    for (int i = 0; i < 2; i++)
#pragma unroll
        for (int j = 0; j < 8; j++)
#pragma unroll
            for (int k = 0; k < 4; k++) acc[i][j][k] = 0.0f;

    // gmem staging indices
    int aRow[2], aCol[2], bRow[2], bCol[2];
#pragma unroll
    for (int l = 0; l < 2; l++) {
        int i = tid + l * 256;
        aRow[l] = i >> 2;  aCol[l] = (i & 3) << 2;     // 128 rows x 16 cols
        bRow[l] = i >> 5;  bCol[l] = (i & 31) << 2;    // 16 rows x 128 cols
    }

    // ldmatrix smem offsets (in elements)
    unsigned offA[2], offB[4];
#pragma unroll
    for (int mt = 0; mt < 2; mt++) {
        int r = wm * 32 + mt * 16 + (lane & 15);
        int ch = (lane >> 4) * 8;
        offA[mt] = r * RS_A + ch;
    }
#pragma unroll
    for (int g = 0; g < 4; g++) {
        int kk = lane & 15;
        int nc = wn * 64 + g * 16 + (lane >> 4) * 8;
        offB[g] = kk * RS_B + nc;
    }
    const unsigned saAhi = (unsigned)__cvta_generic_to_shared(As_hi);
    const unsigned saAlo = (unsigned)__cvta_generic_to_shared(As_lo);
    const unsigned saBhi = (unsigned)__cvta_generic_to_shared(Bs_hi);
    const unsigned saBlo = (unsigned)__cvta_generic_to_shared(Bs_lo);

    const int nChunks = K >> 4;
    float4 ra[2], rb[2];

    // load chunk 0
#pragma unroll
    for (int l = 0; l < 2; l++) {
        if (rowBase + aRow[l] < M)
            ra[l] = *(const float4*)&A[(size_t)(rowBase + aRow[l]) * lda + aCol[l]];
        else
            ra[l] = make_float4(0.f, 0.f, 0.f, 0.f);
        rb[l] = *(const float4*)&B[(size_t)bRow[l] * ldb + colBase + bCol[l]];
    }
    // store chunk 0 to smem
#pragma unroll
    for (int l = 0; l < 2; l++) {
        float v[4] = {ra[l].x, ra[l].y, ra[l].z, ra[l].w};
#pragma unroll
        for (int q = 0; q < 4; q++) {
            __nv_bfloat16 hi = __float2bfloat16(v[q]);
            As_hi[aRow[l] * RS_A + aCol[l] + q] = hi;
            As_lo[aRow[l] * RS_A + aCol[l] + q] =
                __float2bfloat16(v[q] - __bfloat162float(hi));
        }
        float u[4] = {rb[l].x, rb[l].y, rb[l].z, rb[l].w};
#pragma unroll
        for (int q = 0; q < 4; q++) {
            __nv_bfloat16 hi = __float2bfloat16(u[q]);
            Bs_hi[bRow[l] * RS_B + bCol[l] + q] = hi;
            Bs_lo[bRow[l] * RS_B + bCol[l] + q] =
                __float2bfloat16(u[q] - __bfloat162float(hi));
        }
    }
    __syncthreads();

    for (int c = 0; c < nChunks; c++) {
        // prefetch next chunk into regs
        if (c + 1 < nChunks) {
            int k0 = (c + 1) << 4;
#pragma unroll
            for (int l = 0; l < 2; l++) {
                if (rowBase + aRow[l] < M)
                    ra[l] = *(const float4*)&A[(size_t)(rowBase + aRow[l]) * lda + k0 + aCol[l]];
                else
                    ra[l] = make_float4(0.f, 0.f, 0.f, 0.f);
                rb[l] = *(const float4*)&B[(size_t)(k0 + bRow[l]) * ldb + colBase + bCol[l]];
            }
        }

        // fragments + MMA
        unsigned ah[2][4], al[2][4];
#pragma unroll
        for (int mt = 0; mt < 2; mt++) {
            ldsm_x4(ah[mt][0], ah[mt][1], ah[mt][2], ah[mt][3], saAhi + offA[mt] * 2);
            ldsm_x4(al[mt][0], al[mt][1], al[mt][2], al[mt][3], saAlo + offA[mt] * 2);
        }
#pragma unroll
        for (int g = 0; g < 4; g++) {
            unsigned bh[4], bl[4];
            ldsm_x4t(bh[0], bh[1], bh[2], bh[3], saBhi + offB[g] * 2);
            ldsm_x4t(bl[0], bl[1], bl[2], bl[3], saBlo + offB[g] * 2);
#pragma unroll
            for (int mt = 0; mt < 2; mt++) {
                float* a0 = acc[mt][g * 2];
                float* a1 = acc[mt][g * 2 + 1];
                mma16816(a0, ah[mt], bh[0], bh[1]);
                mma16816(a0, ah[mt], bl[0], bl[1]);
                mma16816(a0, al[mt], bh[0], bh[1]);
                mma16816(a1, ah[mt], bh[2], bh[3]);
                mma16816(a1, ah[mt], bl[2], bl[3]);
                mma16816(a1, al[mt], bh[2], bh[3]);
            }
        }
        __syncthreads();

        // commit prefetched chunk to smem
        if (c + 1 < nChunks) {
#pragma unroll
            for (int l = 0; l < 2; l++) {
                float v[4] = {ra[l].x, ra[l].y, ra[l].z, ra[l].w};
#pragma unroll
                for (int q = 0; q < 4; q++) {
                    __nv_bfloat16 hi = __float2bfloat16(v[q]);
                    As_hi[aRow[l] * RS_A + aCol[l] + q] = hi;
                    As_lo[aRow[l] * RS_A + aCol[l] + q] =
                        __float2bfloat16(v[q] - __bfloat162float(hi));
                }
                float u[4] = {rb[l].x, rb[l].y, rb[l].z, rb[l].w};
#pragma unroll
                for (int q = 0; q < 4; q++) {
                    __nv_bfloat16 hi = __float2bfloat16(u[q]);
                    Bs_hi[bRow[l] * RS_B + bCol[l] + q] = hi;
                    Bs_lo[bRow[l] * RS_B + bCol[l] + q] =
                        __float2bfloat16(u[q] - __bfloat162float(hi));
                }
            }
            __syncthreads();
        }
    }

    // epilogue
#pragma unroll
    for (int mt = 0; mt < 2; mt++) {
        int r0 = rowBase + wm * 32 + mt * 16 + (lane >> 2);
        int r1 = r0 + 8;
#pragma unroll
        for (int nt = 0; nt < 8; nt++) {
            int cg = colBase + wn * 64 + nt * 8 + (lane & 3) * 2;
            float b0 = bias[cg], b1 = bias[cg + 1];
            if (r0 < M) {
                float v0 = acc[mt][nt][0] + b0;
                float v1 = acc[mt][nt][1] + b1;
                if (act == 1) { v0 = gelu_exact(v0); v1 = gelu_exact(v1); }
                else if (act == 2) { v0 = tanhf(v0); v1 = tanhf(v1); }
                *(float2*)&C[(size_t)r0 * ldc + cg] = make_float2(v0, v1);
            }
            if (r1 < M) {
                float v0 = acc[mt][nt][2] + b0;
                float v1 = acc[mt][nt][3] + b1;
                if (act == 1) { v0 = gelu_exact(v0); v1 = gelu_exact(v1); }
                else if (act == 2) { v0 = tanhf(v0); v1 = tanhf(v1); }
                *(float2*)&C[(size_t)r1 * ldc + cg] = make_float2(v0, v1);
            }
        }
    }
}

// ---------------- per-relation kernels ----------------
__global__ void gather_kernel(const float* __restrict__ x,
                              const int* __restrict__ ei_r,
                              const float* __restrict__ ea_r)
{
    int e = blockIdx.x, t = threadIdx.x;   // 256 threads
    int src = ei_r[e];
    int dst = ei_r[EE + e];
    g_kvin[e * KVIN + t] = x[(size_t)src * HH + t];
    g_xdst[e * HH + t]   = x[(size_t)dst * HH + t];
    if (t < FF) g_kvin[e * KVIN + HH + t] = ea_r[e * FF + t];
}

__global__ void init_rel_kernel()
{
    int idx = blockIdx.x * 256 + threadIdx.x;   // grid = NN
    g_agg[idx] = 0.0f;
    if (idx < NN * NHH) { g_denom[idx] = 0.0f; g_key[idx] = 0u; }
}

__global__ void score_kernel(const int* __restrict__ dst_r,
                             const float* __restrict__ prior_r)
{
    int e = blockIdx.x, t = threadIdx.x;
    int h = t >> 5, lane = t & 31;
    float p = g_qb[e * HH + t] * g_kb[e * HH + t];
#pragma unroll
    for (int o = 16; o > 0; o >>= 1) p += __shfl_down_sync(0xFFFFFFFFu, p, o);
    if (lane == 0) {
        int dst = dst_r[e];
        float s = p * 0.17677669529663689f * prior_r[h];  // 1/sqrt(32)
        g_scores[e * NHH + h] = s;
        atomicMax(&g_key[dst * NHH + h], enc_f(s));
    }
}

__global__ void ex_kernel(const int* __restrict__ dst_r)
{
    int idx = blockIdx.x * 256 + threadIdx.x;   // E*NH threads
    int e = idx >> 3, h = idx & 7;
    int dst = dst_r[e];
    float m = dec_f(g_key[dst * NHH + h]);
    float ex = expf(g_scores[idx] - m);
    g_scores[idx] = ex;
    atomicAdd(&g_denom[dst * NHH + h], ex);
}

__global__ void scatter_kernel(const int* __restrict__ dst_r)
{
    int e = blockIdx.x, t = threadIdx.x;
    int h = t >> 5;
    int dst = dst_r[e];
    float w = g_scores[e * NHH + h] / (g_denom[dst * NHH + h] + 1e-16f);
    atomicAdd(&g_agg[(size_t)dst * HH + t], w * g_vb[e * HH + t]);
}

// ---------------- inter-relation fusion ----------------
__global__ void inter_kernel(const float* __restrict__ Wir2,
                             const float* __restrict__ bir2)
{
    int n = blockIdx.x, t = threadIdx.x;
    int w = t >> 5, lane = t & 31;
    __shared__ float logit[RR];
    if (w < RR) {
        float s = 0.0f;
        for (int i = lane; i < HH; i += 32)
            s += g_h[(size_t)n * HH + i] * Wir2[i * RR + w];
#pragma unroll
        for (int o = 16; o > 0; o >>= 1) s += __shfl_down_sync(0xFFFFFFFFu, s, o);
        if (lane == 0) logit[w] = s + bir2[w];
    }
    __syncthreads();
    float l[RR]; float mx = -1e30f;
#pragma unroll
    for (int r = 0; r < RR; r++) { l[r] = logit[r]; mx = fmaxf(mx, l[r]); }
    float sum = 0.0f;
#pragma unroll
    for (int r = 0; r < RR; r++) { l[r] = expf(l[r] - mx); sum += l[r]; }
    float inv = 1.0f / sum;
    int c = t;
    const float* ro = g_relout + (size_t)n * (RR * HH);
    float acc = 0.0f;
#pragma unroll
    for (int r = 0; r < RR; r++) acc += l[r] * inv * ro[r * HH + c];
    g_interagg[(size_t)n * HH + c] = acc;
    // meta-paths: 0=rel2+rel3, 1=rel4+rel0, 2=rel1+rel5
    float* pp = g_paths + (size_t)n * 3 * HH;
    pp[c]            = ro[2 * HH + c] + ro[3 * HH + c];
    pp[HH + c]       = ro[4 * HH + c] + ro[0 * HH + c];
    pp[2 * HH + c]   = ro[1 * HH + c] + ro[5 * HH + c];
}

__global__ void meta_kernel(const float* __restrict__ Wa2,
                            const float* __restrict__ gm,
                            const float* __restrict__ bm_)
{
    int n = blockIdx.x, t = threadIdx.x;
    int w = t >> 5, lane = t & 31;
    __shared__ float sl[3];
    __shared__ float red[HH];
    __shared__ float s_mu, s_var;
    if (w < 3) {
        float s = 0.0f;
        for (int i = lane; i < HH / 2; i += 32)
            s += g_t[((size_t)n * 3 + w) * (HH / 2) + i] * Wa2[i];
#pragma unroll
        for (int o = 16; o > 0; o >>= 1) s += __shfl_down_sync(0xFFFFFFFFu, s, o);
        if (lane == 0) sl[w] = s;
    }
    __syncthreads();
    float a0 = sl[0], a1 = sl[1], a2 = sl[2];
    float mx = fmaxf(a0, fmaxf(a1, a2));
    float e0 = expf(a0 - mx), e1 = expf(a1 - mx), e2 = expf(a2 - mx);
    float inv = 1.0f / (e0 + e1 + e2);
    int c = t;
    const float* st = g_stacked + (size_t)n * 3 * HH;
    float mpre = (e0 * st[c] + e1 * st[HH + c] + e2 * st[2 * HH + c]) * inv;
    // LayerNorm over 256
    red[t] = mpre; __syncthreads();
    for (int s = 128; s > 0; s >>= 1) { if (t < s) red[t] += red[t + s]; __syncthreads(); }
    if (t == 0) s_mu = red[0] * (1.0f / HH);
    __syncthreads();
    float d = mpre - s_mu;
    red[t] = d * d; __syncthreads();
    for (int s = 128; s > 0; s >>= 1) { if (t < s) red[t] += red[t + s]; __syncthreads(); }
    if (t == 0) s_var = red[0] * (1.0f / HH);
    __syncthreads();
    float meta = d * rsqrtf(s_var + 1e-5f) * gm[c] + bm_[c];
    g_combin[(size_t)n * 2 * HH + c]      = g_interagg[(size_t)n * HH + c];
    g_combin[(size_t)n * 2 * HH + HH + c] = meta;
}

__global__ void final_kernel(const float* __restrict__ x,
                             const float* __restrict__ g,
                             const float* __restrict__ b,
                             float* __restrict__ out)
{
    int n = blockIdx.x, t = threadIdx.x;
    __shared__ float red[HH];
    __shared__ float s_mu, s_var;
    float v = x[(size_t)n * HH + t] + g_comb[(size_t)n * HH + t];
    red[t] = v; __syncthreads();
    for (int s = 128; s > 0; s >>= 1) { if (t < s) red[t] += red[t + s]; __syncthreads(); }
    if (t == 0) s_mu = red[0] * (1.0f / HH);
    __syncthreads();
    float d = v - s_mu;
    red[t] = d * d; __syncthreads();
    for (int s = 128; s > 0; s >>= 1) { if (t < s) red[t] += red[t + s]; __syncthreads(); }
    if (t == 0) s_var = red[0] * (1.0f / HH);
    __syncthreads();
    out[(size_t)n * HH + t] = d * rsqrtf(s_var + 1e-5f) * g[t] + b[t];
}

// ---------------- host launcher ----------------
static inline void run_gemm(const float* A, int lda, const float* B, int ldb,
                            const float* bias, float* C, int ldc,
                            int M, int Nc, int K, int act)
{
    dim3 grid(Nc / 128, (M + 127) / 128);
    mma_gemm_kernel<<<grid, 256>>>(A, lda, B, ldb, bias, C, ldc, M, Nc, K, act);
}

extern "C" void kernel_launch(void* const* d_in, const int* in_sizes, int n_in,
                              void* d_out, int out_size)
{
    const float* x    = (const float*)d_in[0];
    const int*   ei   = (const int*)d_in[1];
    const float* ea   = (const float*)d_in[2];
    const float* Wq   = (const float*)d_in[3];
    const float* bq   = (const float*)d_in[4];
    const float* Wk   = (const float*)d_in[5];
    const float* bk   = (const float*)d_in[6];
    const float* Wv   = (const float*)d_in[7];
    const float* bv   = (const float*)d_in[8];
    const float* prior= (const float*)d_in[9];
    const float* Wm   = (const float*)d_in[10];
    const float* bm   = (const float*)d_in[11];
    const float* Wir1 = (const float*)d_in[12];
    const float* bir1 = (const float*)d_in[13];
    const float* Wir2 = (const float*)d_in[14];
    const float* bir2 = (const float*)d_in[15];
    const float* Wmp  = (const float*)d_in[16];
    const float* bmp  = (const float*)d_in[17];
    const float* Wa1  = (const float*)d_in[18];
    const float* ba1  = (const float*)d_in[19];
    const float* Wa2  = (const float*)d_in[20];
    const float* gme  = (const float*)d_in[21];
    const float* bme  = (const float*)d_in[22];
    const float* Wc   = (const float*)d_in[23];
    const float* bc   = (const float*)d_in[24];
    const float* gout = (const float*)d_in[25];
    const float* bout = (const float*)d_in[26];
    float* out = (float*)d_out;

    float *p_kvin, *p_xdst, *p_kb, *p_vb, *p_qb, *p_agg, *p_relout, *p_h,
          *p_paths, *p_stacked, *p_t, *p_combin, *p_comb;
    cudaGetSymbolAddress((void**)&p_kvin, g_kvin);
    cudaGetSymbolAddress((void**)&p_xdst, g_xdst);
    cudaGetSymbolAddress((void**)&p_kb, g_kb);
    cudaGetSymbolAddress((void**)&p_vb, g_vb);
    cudaGetSymbolAddress((void**)&p_qb, g_qb);
    cudaGetSymbolAddress((void**)&p_agg, g_agg);
    cudaGetSymbolAddress((void**)&p_relout, g_relout);
    cudaGetSymbolAddress((void**)&p_h, g_h);
    cudaGetSymbolAddress((void**)&p_paths, g_paths);
    cudaGetSymbolAddress((void**)&p_stacked, g_stacked);
    cudaGetSymbolAddress((void**)&p_t, g_t);
    cudaGetSymbolAddress((void**)&p_combin, g_combin);
    cudaGetSymbolAddress((void**)&p_comb, g_comb);

    for (int r = 0; r < RR; r++) {
        const int* ei_r  = ei + (size_t)r * 2 * EE;
        const int* dst_r = ei_r + EE;
        const float* ea_r = ea + (size_t)r * EE * FF;

        gather_kernel<<<EE, 256>>>(x, ei_r, ea_r);
        run_gemm(p_kvin, KVIN, Wk + (size_t)r * KVIN * HH, HH, bk + r * HH,
                 p_kb, HH, EE, HH, KVIN, 0);
        run_gemm(p_kvin, KVIN, Wv + (size_t)r * KVIN * HH, HH, bv + r * HH,
                 p_vb, HH, EE, HH, KVIN, 0);
        run_gemm(p_xdst, HH, Wq + (size_t)r * HH * HH, HH, bq + r * HH,
                 p_qb, HH, EE, HH, HH, 0);
        init_rel_kernel<<<NN, 256>>>();
        score_kernel<<<EE, 256>>>(dst_r, prior + r * NHH);
        ex_kernel<<<(EE * NHH) / 256, 256>>>(dst_r);
        scatter_kernel<<<EE, 256>>>(dst_r);
        // rel_out[r] = gelu(agg @ Wm + bm) -> column slice of [N, R*H]
        run_gemm(p_agg, HH, Wm + (size_t)r * HH * HH, HH, bm + r * HH,
                 p_relout + r * HH, RR * HH, NN, HH, HH, 1);
    }

    // h = gelu(all_rel @ W_ir1 + b_ir1)
    run_gemm(p_relout, RR * HH, Wir1, HH, bir1, p_h, HH, NN, HH, RR * HH, 1);
    // inter softmax + inter_agg + meta-path sums
    inter_kernel<<<NN, 256>>>(Wir2, bir2);
    // stacked[p] = paths[p] @ Wmp[p] + bmp[p]
    for (int p = 0; p < 3; p++)
        run_gemm(p_paths + p * HH, 3 * HH, Wmp + (size_t)p * HH * HH, HH,
                 bmp + p * HH, p_stacked + p * HH, 3 * HH, NN, HH, HH, 0);
    // t = tanh(stacked @ Wa1 + ba1), rows = (n,p)
    run_gemm(p_stacked, HH, Wa1, HH / 2, ba1, p_t, HH / 2, 3 * NN, HH / 2, HH, 2);
    // meta attention + LN + build combined input
    meta_kernel<<<NN, 256>>>(Wa2, gme, bme);
    // combined = gelu([inter_agg, meta] @ Wc + bc)
    run_gemm(p_combin, 2 * HH, Wc, HH, bc, p_comb, HH, NN, HH, 2 * HH, 1);
    // out = LN(x + combined)
    final_kernel<<<NN, 256>>>(x, gout, bout, out);
}

// round 3
// speedup vs baseline: 1.6899x; 1.1404x over previous
#include <cuda_runtime.h>
#include <cuda_bf16.h>
#include <math.h>

#define NN 50000
#define RR 6
#define EE 32768
#define HH 256
#define FF 16
#define NHH 8
#define KVIN (HH + FF)      // 272

typedef __nv_bfloat16 bf16;

// ---------------- fp32 scratch ----------------
__device__ float g_kb[EE * HH];
__device__ float g_vb[EE * HH];
__device__ float g_qb[EE * HH];
__device__ float g_scores[EE * NHH];
__device__ float g_denom[NN * NHH];
__device__ unsigned g_key[NN * NHH];
__device__ float g_agg[NN * HH];
__device__ float g_relout[(size_t)NN * RR * HH];   // [N, R*H]
__device__ float g_h[NN * HH];
__device__ float g_stacked[NN * 3 * HH];
__device__ float g_t[NN * 3 * (HH / 2)];
__device__ float g_interagg[NN * HH];
__device__ float g_comb[NN * HH];

// ---------------- bf16 hi/lo planes (activations) ----------------
__device__ bf16 g_kvin_h[EE * KVIN],  g_kvin_l[EE * KVIN];
__device__ bf16 g_xdst_h[EE * HH],    g_xdst_l[EE * HH];
__device__ bf16 g_agg_h[NN * HH],     g_agg_l[NN * HH];
__device__ bf16 g_relout_h[(size_t)NN * RR * HH], g_relout_l[(size_t)NN * RR * HH];
__device__ bf16 g_paths_h[NN * 3 * HH],  g_paths_l[NN * 3 * HH];
__device__ bf16 g_stacked_h[NN * 3 * HH], g_stacked_l[NN * 3 * HH];
__device__ bf16 g_combin_h[NN * 2 * HH],  g_combin_l[NN * 2 * HH];

// ---------------- bf16 hi/lo planes (weights) ----------------
__device__ bf16 g_Wq_h[RR * HH * HH],     g_Wq_l[RR * HH * HH];
__device__ bf16 g_Wk_h[RR * KVIN * HH],   g_Wk_l[RR * KVIN * HH];
__device__ bf16 g_Wv_h[RR * KVIN * HH],   g_Wv_l[RR * KVIN * HH];
__device__ bf16 g_Wm_h[RR * HH * HH],     g_Wm_l[RR * HH * HH];
__device__ bf16 g_Wir1_h[RR * HH * HH],   g_Wir1_l[RR * HH * HH];
__device__ bf16 g_Wmp_h[3 * HH * HH],     g_Wmp_l[3 * HH * HH];
__device__ bf16 g_Wa1_h[HH * HH / 2],     g_Wa1_l[HH * HH / 2];
__device__ bf16 g_Wc_h[2 * HH * HH],      g_Wc_l[2 * HH * HH];

__device__ __forceinline__ float gelu_exact(float x) {
    return 0.5f * x * (1.0f + erff(x * 0.70710678118654752f));
}
__device__ __forceinline__ void split2(float v, bf16& hi, bf16& lo) {
    hi = __float2bfloat16(v);
    lo = __float2bfloat16(v - __bfloat162float(hi));
}
__device__ __forceinline__ unsigned enc_f(float f) {
    unsigned b = __float_as_uint(f);
    return (b & 0x80000000u) ? ~b : (b | 0x80000000u);
}
__device__ __forceinline__ float dec_f(unsigned u) {
    return (u & 0x80000000u) ? __uint_as_float(u ^ 0x80000000u)
                             : __uint_as_float(~u);
}

// ================= tensor-core GEMM, bf16-split inputs, cp.async 4-stage =====
#define RS_A 24
#define RS_B 136
#define STAGE_BYTES 20992   // Ahi 6144 | Alo 6144 | Bhi 4352 | Blo 4352
#define GEMM_SMEM (4 * STAGE_BYTES)

__device__ __forceinline__ void cp16(unsigned d, const void* s, unsigned sz) {
    asm volatile("cp.async.cg.shared.global [%0], [%1], 16, %2;"
                 :: "r"(d), "l"(s), "r"(sz));
}
__device__ __forceinline__ void ldsm_x4(unsigned& r0, unsigned& r1,
                                        unsigned& r2, unsigned& r3,
                                        unsigned addr) {
    asm volatile("ldmatrix.sync.aligned.m8n8.x4.shared.b16 {%0,%1,%2,%3}, [%4];"
                 : "=r"(r0), "=r"(r1), "=r"(r2), "=r"(r3) : "r"(addr));
}
__device__ __forceinline__ void ldsm_x4t(unsigned& r0, unsigned& r1,
                                         unsigned& r2, unsigned& r3,
                                         unsigned addr) {
    asm volatile("ldmatrix.sync.aligned.m8n8.x4.trans.shared.b16 {%0,%1,%2,%3}, [%4];"
                 : "=r"(r0), "=r"(r1), "=r"(r2), "=r"(r3) : "r"(addr));
}
__device__ __forceinline__ void mma16816(float* c, const unsigned* a,
                                         unsigned b0, unsigned b1) {
    asm volatile(
        "mma.sync.aligned.m16n8k16.row.col.f32.bf16.bf16.f32 "
        "{%0,%1,%2,%3},{%4,%5,%6,%7},{%8,%9},{%0,%1,%2,%3};"
        : "+f"(c[0]), "+f"(c[1]), "+f"(c[2]), "+f"(c[3])
        : "r"(a[0]), "r"(a[1]), "r"(a[2]), "r"(a[3]), "r"(b0), "r"(b1));
}

// C[M,Nc] = act(A@B + bias); A hi/lo bf16 [M,K], B hi/lo bf16 [K,Nc].
// Optional dual-write of bf16 hi/lo copies of C (Chi/Clo, ldc2).
__global__ __launch_bounds__(256)
void mma_gemm_bf16(const bf16* __restrict__ Ahi, const bf16* __restrict__ Alo, int lda,
                   const bf16* __restrict__ Bhi, const bf16* __restrict__ Blo, int ldb,
                   const float* __restrict__ bias,
                   float* __restrict__ C, int ldc,
                   bf16* __restrict__ Chi, bf16* __restrict__ Clo, int ldc2,
                   int M, int Nc, int K, int act)
{
    extern __shared__ __align__(128) char smem[];
    const unsigned smemBase = (unsigned)__cvta_generic_to_shared(smem);

    const int tid = threadIdx.x;
    const int lane = tid & 31;
    const int w = tid >> 5;
    const int wm = w & 3;
    const int wn = w >> 2;
    const int rowBase = blockIdx.y * 128;
    const int colBase = blockIdx.x * 128;
    const int nChunks = K >> 4;

    float acc[2][8][4];
#pragma unroll
    for (int i = 0; i < 2; i++)
#pragma unroll
        for (int j = 0; j < 8; j++)
#pragma unroll
            for (int q = 0; q < 4; q++) acc[i][j][q] = 0.0f;

    unsigned offA[2], offB[4];
#pragma unroll
    for (int mt = 0; mt < 2; mt++)
        offA[mt] = (wm * 32 + mt * 16 + (lane & 15)) * RS_A + (lane >> 4) * 8;
#pragma unroll
    for (int g = 0; g < 4; g++)
        offB[g] = (lane & 15) * RS_B + wn * 64 + g * 16 + (lane >> 4) * 8;

    // per-thread copy coordinates
    const int aRow = tid >> 1;
    const int aCh  = (tid & 1) << 3;
    const int bRow = tid >> 4;
    const int bCh  = (tid & 15) << 3;
    const int aSafe = (rowBase + aRow < M) ? (rowBase + aRow) : 0;
    const unsigned aSz = (rowBase + aRow < M) ? 16u : 0u;

    auto issue_stage = [&](int c) {
        if (c < nChunks) {
            const int k0 = c << 4;
            const unsigned sb = smemBase + (c & 3) * STAGE_BYTES;
            size_t ao = (size_t)aSafe * lda + k0 + aCh;
            unsigned da = sb + (aRow * RS_A + aCh) * 2;
            cp16(da,        Ahi + ao, aSz);
            cp16(da + 6144, Alo + ao, aSz);
            size_t bo = (size_t)(k0 + bRow) * ldb + colBase + bCh;
            unsigned db = sb + 12288 + (bRow * RS_B + bCh) * 2;
            cp16(db,        Bhi + bo, 16u);
            cp16(db + 4352, Blo + bo, 16u);
        }
        asm volatile("cp.async.commit_group;" ::);
    };

    issue_stage(0); issue_stage(1); issue_stage(2);

    for (int k = 0; k < nChunks; k++) {
        asm volatile("cp.async.wait_group 2;" ::);
        __syncthreads();
        issue_stage(k + 3);

        const unsigned sb = smemBase + (k & 3) * STAGE_BYTES;
        unsigned ah[2][4], al[2][4];
#pragma unroll
        for (int mt = 0; mt < 2; mt++) {
            ldsm_x4(ah[mt][0], ah[mt][1], ah[mt][2], ah[mt][3], sb + offA[mt] * 2);
            ldsm_x4(al[mt][0], al[mt][1], al[mt][2], al[mt][3], sb + 6144 + offA[mt] * 2);
        }
#pragma unroll
        for (int g = 0; g < 4; g++) {
            unsigned bh[4], bl[4];
            ldsm_x4t(bh[0], bh[1], bh[2], bh[3], sb + 12288 + offB[g] * 2);
            ldsm_x4t(bl[0], bl[1], bl[2], bl[3], sb + 16640 + offB[g] * 2);
#pragma unroll
            for (int mt = 0; mt < 2; mt++) {
                float* a0 = acc[mt][g * 2];
                float* a1 = acc[mt][g * 2 + 1];
                mma16816(a0, ah[mt], bh[0], bh[1]);
                mma16816(a0, ah[mt], bl[0], bl[1]);
                mma16816(a0, al[mt], bh[0], bh[1]);
                mma16816(a1, ah[mt], bh[2], bh[3]);
                mma16816(a1, ah[mt], bl[2], bl[3]);
                mma16816(a1, al[mt], bh[2], bh[3]);
            }
        }
    }

    // epilogue
#pragma unroll
    for (int mt = 0; mt < 2; mt++) {
        int r0 = rowBase + wm * 32 + mt * 16 + (lane >> 2);
#pragma unroll
        for (int half = 0; half < 2; half++) {
            int r = r0 + half * 8;
            if (r >= M) continue;
#pragma unroll
            for (int nt = 0; nt < 8; nt++) {
                int cg = colBase + wn * 64 + nt * 8 + (lane & 3) * 2;
                float v0 = acc[mt][nt][half * 2]     + bias[cg];
                float v1 = acc[mt][nt][half * 2 + 1] + bias[cg + 1];
                if (act == 1) { v0 = gelu_exact(v0); v1 = gelu_exact(v1); }
                else if (act == 2) { v0 = tanhf(v0); v1 = tanhf(v1); }
                *(float2*)&C[(size_t)r * ldc + cg] = make_float2(v0, v1);
                if (Chi) {
                    bf16 h0, l0, h1, l1;
                    split2(v0, h0, l0); split2(v1, h1, l1);
                    __nv_bfloat162 ph; ph.x = h0; ph.y = h1;
                    __nv_bfloat162 pl; pl.x = l0; pl.y = l1;
                    *(__nv_bfloat162*)&Chi[(size_t)r * ldc2 + cg] = ph;
                    *(__nv_bfloat162*)&Clo[(size_t)r * ldc2 + cg] = pl;
                }
            }
        }
    }
}

// ---------------- elementwise split (weights / agg) ----------------
__global__ void split_kernel(const float* __restrict__ src,
                             bf16* __restrict__ hi, bf16* __restrict__ lo, int n)
{
    int i = blockIdx.x * 256 + threadIdx.x;
    if (i < n) split2(src[i], hi[i], lo[i]);
}

// ---------------- per-relation kernels ----------------
__global__ void gather_kernel(const float* __restrict__ x,
                              const int* __restrict__ ei_r,
                              const float* __restrict__ ea_r)
{
    int e = blockIdx.x, t = threadIdx.x;
    int src = ei_r[e];
    int dst = ei_r[EE + e];
    split2(x[(size_t)src * HH + t], g_kvin_h[e * KVIN + t], g_kvin_l[e * KVIN + t]);
    split2(x[(size_t)dst * HH + t], g_xdst_h[e * HH + t],   g_xdst_l[e * HH + t]);
    if (t < FF)
        split2(ea_r[e * FF + t], g_kvin_h[e * KVIN + HH + t], g_kvin_l[e * KVIN + HH + t]);
}

__global__ void init_rel_kernel()
{
    int idx = blockIdx.x * 256 + threadIdx.x;
    g_agg[idx] = 0.0f;
    if (idx < NN * NHH) { g_denom[idx] = 0.0f; g_key[idx] = 0u; }
}

__global__ void score_kernel(const int* __restrict__ dst_r,
                             const float* __restrict__ prior_r)
{
    int e = blockIdx.x, t = threadIdx.x;
    int h = t >> 5, lane = t & 31;
    float p = g_qb[e * HH + t] * g_kb[e * HH + t];
#pragma unroll
    for (int o = 16; o > 0; o >>= 1) p += __shfl_down_sync(0xFFFFFFFFu, p, o);
    if (lane == 0) {
        int dst = dst_r[e];
        float s = p * 0.17677669529663689f * prior_r[h];
        g_scores[e * NHH + h] = s;
        atomicMax(&g_key[dst * NHH + h], enc_f(s));
    }
}

__global__ void ex_kernel(const int* __restrict__ dst_r)
{
    int idx = blockIdx.x * 256 + threadIdx.x;
    int e = idx >> 3, h = idx & 7;
    int dst = dst_r[e];
    float m = dec_f(g_key[dst * NHH + h]);
    float ex = expf(g_scores[idx] - m);
    g_scores[idx] = ex;
    atomicAdd(&g_denom[dst * NHH + h], ex);
}

__global__ void scatter_kernel(const int* __restrict__ dst_r)
{
    int e = blockIdx.x, t = threadIdx.x;
    int h = t >> 5;
    int dst = dst_r[e];
    float w = g_scores[e * NHH + h] / (g_denom[dst * NHH + h] + 1e-16f);
    atomicAdd(&g_agg[(size_t)dst * HH + t], w * g_vb[e * HH + t]);
}

// ---------------- inter-relation fusion ----------------
__global__ void inter_kernel(const float* __restrict__ Wir2,
                             const float* __restrict__ bir2)
{
    int n = blockIdx.x, t = threadIdx.x;
    int w = t >> 5, lane = t & 31;
    __shared__ float logit[RR];
    if (w < RR) {
        float s = 0.0f;
        for (int i = lane; i < HH; i += 32)
            s += g_h[(size_t)n * HH + i] * Wir2[i * RR + w];
#pragma unroll
        for (int o = 16; o > 0; o >>= 1) s += __shfl_down_sync(0xFFFFFFFFu, s, o);
        if (lane == 0) logit[w] = s + bir2[w];
    }
    __syncthreads();
    float l[RR]; float mx = -1e30f;
#pragma unroll
    for (int r = 0; r < RR; r++) { l[r] = logit[r]; mx = fmaxf(mx, l[r]); }
    float sum = 0.0f;
#pragma unroll
    for (int r = 0; r < RR; r++) { l[r] = expf(l[r] - mx); sum += l[r]; }
    float inv = 1.0f / sum;
    int c = t;
    const float* ro = g_relout + (size_t)n * (RR * HH);
    float acc = 0.0f;
#pragma unroll
    for (int r = 0; r < RR; r++) acc += l[r] * inv * ro[r * HH + c];
    g_interagg[(size_t)n * HH + c] = acc;
    size_t base = (size_t)n * 3 * HH;
    split2(ro[2 * HH + c] + ro[3 * HH + c], g_paths_h[base + c],          g_paths_l[base + c]);
    split2(ro[4 * HH + c] + ro[0 * HH + c], g_paths_h[base + HH + c],     g_paths_l[base + HH + c]);
    split2(ro[1 * HH + c] + ro[5 * HH + c], g_paths_h[base + 2 * HH + c], g_paths_l[base + 2 * HH + c]);
}

__global__ void meta_kernel(const float* __restrict__ Wa2,
                            const float* __restrict__ gm,
                            const float* __restrict__ bm_)
{
    int n = blockIdx.x, t = threadIdx.x;
    int w = t >> 5, lane = t & 31;
    __shared__ float sl[3];
    __shared__ float red[HH];
    __shared__ float s_mu, s_var;
    if (w < 3) {
        float s = 0.0f;
        for (int i = lane; i < HH / 2; i += 32)
            s += g_t[((size_t)n * 3 + w) * (HH / 2) + i] * Wa2[i];
#pragma unroll
        for (int o = 16; o > 0; o >>= 1) s += __shfl_down_sync(0xFFFFFFFFu, s, o);
        if (lane == 0) sl[w] = s;
    }
    __syncthreads();
    float a0 = sl[0], a1 = sl[1], a2 = sl[2];
    float mx = fmaxf(a0, fmaxf(a1, a2));
    float e0 = expf(a0 - mx), e1 = expf(a1 - mx), e2 = expf(a2 - mx);
    float inv = 1.0f / (e0 + e1 + e2);
    int c = t;
    const float* st = g_stacked + (size_t)n * 3 * HH;
    float mpre = (e0 * st[c] + e1 * st[HH + c] + e2 * st[2 * HH + c]) * inv;
    red[t] = mpre; __syncthreads();
    for (int s = 128; s > 0; s >>= 1) { if (t < s) red[t] += red[t + s]; __syncthreads(); }
    if (t == 0) s_mu = red[0] * (1.0f / HH);
    __syncthreads();
    float d = mpre - s_mu;
    red[t] = d * d; __syncthreads();
    for (int s = 128; s > 0; s >>= 1) { if (t < s) red[t] += red[t + s]; __syncthreads(); }
    if (t == 0) s_var = red[0] * (1.0f / HH);
    __syncthreads();
    float meta = d * rsqrtf(s_var + 1e-5f) * gm[c] + bm_[c];
    size_t base = (size_t)n * 2 * HH;
    split2(g_interagg[(size_t)n * HH + c], g_combin_h[base + c],      g_combin_l[base + c]);
    split2(meta,                           g_combin_h[base + HH + c], g_combin_l[base + HH + c]);
}

__global__ void final_kernel(const float* __restrict__ x,
                             const float* __restrict__ g,
                             const float* __restrict__ b,
                             float* __restrict__ out)
{
    int n = blockIdx.x, t = threadIdx.x;
    __shared__ float red[HH];
    __shared__ float s_mu, s_var;
    float v = x[(size_t)n * HH + t] + g_comb[(size_t)n * HH + t];
    red[t] = v; __syncthreads();
    for (int s = 128; s > 0; s >>= 1) { if (t < s) red[t] += red[t + s]; __syncthreads(); }
    if (t == 0) s_mu = red[0] * (1.0f / HH);
    __syncthreads();
    float d = v - s_mu;
    red[t] = d * d; __syncthreads();
    for (int s = 128; s > 0; s >>= 1) { if (t < s) red[t] += red[t + s]; __syncthreads(); }
    if (t == 0) s_var = red[0] * (1.0f / HH);
    __syncthreads();
    out[(size_t)n * HH + t] = d * rsqrtf(s_var + 1e-5f) * g[t] + b[t];
}

// ---------------- host ----------------
static inline void run_gemm(const bf16* Ah, const bf16* Al, int lda,
                            const bf16* Bh, const bf16* Bl, int ldb,
                            const float* bias, float* C, int ldc,
                            bf16* Ch, bf16* Cl, int ldc2,
                            int M, int Nc, int K, int act)
{
    dim3 grid(Nc / 128, (M + 127) / 128);
    mma_gemm_bf16<<<grid, 256, GEMM_SMEM>>>(Ah, Al, lda, Bh, Bl, ldb, bias,
                                            C, ldc, Ch, Cl, ldc2, M, Nc, K, act);
}
static inline void run_split(const float* src, bf16* hi, bf16* lo, int n)
{
    split_kernel<<<(n + 255) / 256, 256>>>(src, hi, lo, n);
}

extern "C" void kernel_launch(void* const* d_in, const int* in_sizes, int n_in,
                              void* d_out, int out_size)
{
    const float* x    = (const float*)d_in[0];
    const int*   ei   = (const int*)d_in[1];
    const float* ea   = (const float*)d_in[2];
    const float* Wq   = (const float*)d_in[3];
    const float* bq   = (const float*)d_in[4];
    const float* Wk   = (const float*)d_in[5];
    const float* bk   = (const float*)d_in[6];
    const float* Wv   = (const float*)d_in[7];
    const float* bv   = (const float*)d_in[8];
    const float* prior= (const float*)d_in[9];
    const float* Wm   = (const float*)d_in[10];
    const float* bm   = (const float*)d_in[11];
    const float* Wir1 = (const float*)d_in[12];
    const float* bir1 = (const float*)d_in[13];
    const float* Wir2 = (const float*)d_in[14];
    const float* bir2 = (const float*)d_in[15];
    const float* Wmp  = (const float*)d_in[16];
    const float* bmp  = (const float*)d_in[17];
    const float* Wa1  = (const float*)d_in[18];
    const float* ba1  = (const float*)d_in[19];
    const float* Wa2  = (const float*)d_in[20];
    const float* gme  = (const float*)d_in[21];
    const float* bme  = (const float*)d_in[22];
    const float* Wc   = (const float*)d_in[23];
    const float* bc   = (const float*)d_in[24];
    const float* gout = (const float*)d_in[25];
    const float* bout = (const float*)d_in[26];
    float* out = (float*)d_out;

    cudaFuncSetAttribute(mma_gemm_bf16,
                         cudaFuncAttributeMaxDynamicSharedMemorySize, GEMM_SMEM);

    // symbol addresses
#define SYM(p, s) { void* tmp; cudaGetSymbolAddress(&tmp, s); p = (decltype(p))tmp; }
    float *p_kb, *p_vb, *p_qb, *p_agg, *p_relout, *p_h, *p_stacked, *p_t,
          *p_comb;
    SYM(p_kb, g_kb); SYM(p_vb, g_vb); SYM(p_qb, g_qb); SYM(p_agg, g_agg);
    SYM(p_relout, g_relout); SYM(p_h, g_h); SYM(p_stacked, g_stacked);
    SYM(p_t, g_t); SYM(p_comb, g_comb);
    bf16 *kvin_h, *kvin_l, *xdst_h, *xdst_l, *agg_h, *agg_l,
         *relout_h, *relout_l, *paths_h, *paths_l, *stacked_h, *stacked_l,
         *combin_h, *combin_l;
    SYM(kvin_h, g_kvin_h); SYM(kvin_l, g_kvin_l);
    SYM(xdst_h, g_xdst_h); SYM(xdst_l, g_xdst_l);
    SYM(agg_h, g_agg_h);   SYM(agg_l, g_agg_l);
    SYM(relout_h, g_relout_h); SYM(relout_l, g_relout_l);
    SYM(paths_h, g_paths_h);   SYM(paths_l, g_paths_l);
    SYM(stacked_h, g_stacked_h); SYM(stacked_l, g_stacked_l);
    SYM(combin_h, g_combin_h);   SYM(combin_l, g_combin_l);
    bf16 *Wq_h, *Wq_l, *Wk_h, *Wk_l, *Wv_h, *Wv_l, *Wm_h, *Wm_l,
         *Wir1_h, *Wir1_l, *Wmp_h, *Wmp_l, *Wa1_h, *Wa1_l, *Wc_h, *Wc_l;
    SYM(Wq_h, g_Wq_h); SYM(Wq_l, g_Wq_l);
    SYM(Wk_h, g_Wk_h); SYM(Wk_l, g_Wk_l);
    SYM(Wv_h, g_Wv_h); SYM(Wv_l, g_Wv_l);
    SYM(Wm_h, g_Wm_h); SYM(Wm_l, g_Wm_l);
    SYM(Wir1_h, g_Wir1_h); SYM(Wir1_l, g_Wir1_l);
    SYM(Wmp_h, g_Wmp_h);   SYM(Wmp_l, g_Wmp_l);
    SYM(Wa1_h, g_Wa1_h);   SYM(Wa1_l, g_Wa1_l);
    SYM(Wc_h, g_Wc_h);     SYM(Wc_l, g_Wc_l);
#undef SYM

    // weight splits
    run_split(Wq,   Wq_h,   Wq_l,   RR * HH * HH);
    run_split(Wk,   Wk_h,   Wk_l,   RR * KVIN * HH);
    run_split(Wv,   Wv_h,   Wv_l,   RR * KVIN * HH);
    run_split(Wm,   Wm_h,   Wm_l,   RR * HH * HH);
    run_split(Wir1, Wir1_h, Wir1_l, RR * HH * HH);
    run_split(Wmp,  Wmp_h,  Wmp_l,  3 * HH * HH);
    run_split(Wa1,  Wa1_h,  Wa1_l,  HH * HH / 2);
    run_split(Wc,   Wc_h,   Wc_l,   2 * HH * HH);

    for (int r = 0; r < RR; r++) {
        const int* ei_r  = ei + (size_t)r * 2 * EE;
        const int* dst_r = ei_r + EE;
        const float* ea_r = ea + (size_t)r * EE * FF;

        gather_kernel<<<EE, 256>>>(x, ei_r, ea_r);
        run_gemm(kvin_h, kvin_l, KVIN, Wk_h + (size_t)r * KVIN * HH,
                 Wk_l + (size_t)r * KVIN * HH, HH, bk + r * HH,
                 p_kb, HH, nullptr, nullptr, 0, EE, HH, KVIN, 0);
        run_gemm(kvin_h, kvin_l, KVIN, Wv_h + (size_t)r * KVIN * HH,
                 Wv_l + (size_t)r * KVIN * HH, HH, bv + r * HH,
                 p_vb, HH, nullptr, nullptr, 0, EE, HH, KVIN, 0);
        run_gemm(xdst_h, xdst_l, HH, Wq_h + (size_t)r * HH * HH,
                 Wq_l + (size_t)r * HH * HH, HH, bq + r * HH,
                 p_qb, HH, nullptr, nullptr, 0, EE, HH, HH, 0);
        init_rel_kernel<<<NN, 256>>>();
        score_kernel<<<EE, 256>>>(dst_r, prior + r * NHH);
        ex_kernel<<<(EE * NHH) / 256, 256>>>(dst_r);
        scatter_kernel<<<EE, 256>>>(dst_r);
        run_split(p_agg, agg_h, agg_l, NN * HH);
        // rel_out[r] = gelu(agg @ Wm + bm) -> fp32 + bf16 planes, col slice r*H
        run_gemm(agg_h, agg_l, HH, Wm_h + (size_t)r * HH * HH,
                 Wm_l + (size_t)r * HH * HH, HH, bm + r * HH,
                 p_relout + r * HH, RR * HH,
                 relout_h + r * HH, relout_l + r * HH, RR * HH,
                 NN, HH, HH, 1);
    }

    // h = gelu(all_rel @ W_ir1 + b_ir1)
    run_gemm(relout_h, relout_l, RR * HH, Wir1_h, Wir1_l, HH, bir1,
             p_h, HH, nullptr, nullptr, 0, NN, HH, RR * HH, 1);
    inter_kernel<<<NN, 256>>>(Wir2, bir2);
    // stacked[p] = paths[p] @ Wmp[p] + bmp[p] (fp32 + bf16 planes)
    for (int p = 0; p < 3; p++)
        run_gemm(paths_h + p * HH, paths_l + p * HH, 3 * HH,
                 Wmp_h + (size_t)p * HH * HH, Wmp_l + (size_t)p * HH * HH, HH,
                 bmp + p * HH, p_stacked + p * HH, 3 * HH,
                 stacked_h + p * HH, stacked_l + p * HH, 3 * HH,
                 NN, HH, HH, 0);
    // t = tanh(stacked @ Wa1 + ba1)
    run_gemm(stacked_h, stacked_l, HH, Wa1_h, Wa1_l, HH / 2, ba1,
             p_t, HH / 2, nullptr, nullptr, 0, 3 * NN, HH / 2, HH, 2);
    meta_kernel<<<NN, 256>>>(Wa2, gme, bme);
    // combined = gelu([inter_agg, meta] @ Wc + bc)
    run_gemm(combin_h, combin_l, 2 * HH, Wc_h, Wc_l, HH, bc,
             p_comb, HH, nullptr, nullptr, 0, NN, HH, 2 * HH, 1);
    final_kernel<<<NN, 256>>>(x, gout, bout, out);
}